// round 10
// baseline (speedup 1.0000x reference)
#include <cuda_runtime.h>
#include <math.h>

#define SS 128
#define POS_BANDS 10
#define D_ENC 63
#define D_VD 27
#define HID 64
#define FEAT 15

__device__ float g_dt;

// ---- weights in constant memory (uniform-const port, off the L1tex path) ----
__constant__ float W1c[D_ENC * HID];
__constant__ float b1c[HID];
__constant__ float W2c[HID * 16];
__constant__ float b2c[16];
__constant__ float V1c[FEAT * HID];    // rows 0..14 only
__constant__ float V2c[HID * 3];
__constant__ float c2c[3];

// ---------------- packed f32x2 FMA ----------------
struct F2 { union { float2 f; unsigned long long u; }; };
__device__ __forceinline__ F2 f2mk(float x, float y) { F2 r; r.f.x = x; r.f.y = y; return r; }
__device__ __forceinline__ F2 f2dup(float x) { return f2mk(x, x); }
__device__ __forceinline__ void fma2(F2& d, const F2 a, const F2 b) {
    asm("fma.rn.f32x2 %0, %1, %2, %0;" : "+l"(d.u) : "l"(a.u), "l"(b.u));
}

// one layer-1 row: h[0..63] += val * W1[k][0..63]  (weights warp-uniform -> LDCU)
__device__ __forceinline__ void accum_row(F2* h, int k, float val) {
    const F2 ad = f2dup(val);
#pragma unroll
    for (int q = 0; q < 16; q++) {
        const float4 w = *(const float4*)&W1c[k * HID + 4 * q];
        fma2(h[2 * q + 0], ad, f2mk(w.x, w.y));
        fma2(h[2 * q + 1], ad, f2mk(w.z, w.w));
    }
}

// ---------------------------------------------------------------------------
__global__ void reduce_dt_kernel(const float* __restrict__ tmin,
                                 const float* __restrict__ tmax, int n) {
    __shared__ float sh[256];
    float s = 0.f;
    for (int i = threadIdx.x; i < n; i += 256) s += tmax[i] - tmin[i];
    sh[threadIdx.x] = s;
    __syncthreads();
    for (int o = 128; o > 0; o >>= 1) {
        if (threadIdx.x < o) sh[threadIdx.x] += sh[threadIdx.x + o];
        __syncthreads();
    }
    if (threadIdx.x == 0) g_dt = sh[0] / (float)n / (float)SS;
}

// ---------------------------------------------------------------------------
struct __align__(16) SmemT {
    float basev[64];       // c1 + vd_enc @ V1[15:42]
    float vd[28];
    float wagg[4];
    float red[16];
};

__global__ void __launch_bounds__(SS, 4)
raymarch_kernel(const float* __restrict__ orig, const float* __restrict__ dirs,
                const float* __restrict__ tmin, const float* __restrict__ tmax,
                const float* __restrict__ V1, const float* __restrict__ c1,
                float* __restrict__ out, int N) {
    __shared__ SmemT sm;
    const int r = blockIdx.x;
    const int tid = threadIdx.x;
    const int lane = tid & 31;
    const int warp = tid >> 5;

    const float dx = dirs[r * 3 + 0], dy = dirs[r * 3 + 1], dz = dirs[r * 3 + 2];
    const float inv = 1.f / (sqrtf(dx * dx + dy * dy + dz * dz) + 1e-8f);
    if (tid < D_VD) {
        const int p = tid / 3, c = tid % 3;
        float v = ((c == 0) ? dx : (c == 1) ? dy : dz) * inv;
        float val;
        if (p == 0) val = v;
        else {
            const int band = (p - 1) >> 1;
            float sn, cs;
            sincosf(v * (float)(1 << band), &sn, &cs);
            val = ((p - 1) & 1) ? cs : sn;
        }
        sm.vd[tid] = val;
    }
    __syncthreads();

    // ---- base = c1 + vd_enc @ V1[15:42]  (per-ray constant; coalesced LDG) ----
    if (tid < HID) {
        float acc = c1[tid];
#pragma unroll
        for (int k = 0; k < D_VD; k++) acc += sm.vd[k] * V1[(FEAT + k) * HID + tid];
        sm.basev[tid] = acc;
    }
    __syncthreads();

    // ======== fully per-thread: encoding fused into layer 1 ========
    // h = relu(b1 + ENC @ W1), ENC generated on the fly by angle doubling
    F2 h[32];
#pragma unroll
    for (int q = 0; q < 32; q++) h[q] = f2mk(b1c[2 * q], b1c[2 * q + 1]);

    {
        const float t0 = tmin[r], t1 = tmax[r];
        const float tt = t0 + (float)tid * (1.f / (SS - 1)) * (t1 - t0);
        const float px = orig[r * 3 + 0] + dx * tt;
        const float py = orig[r * 3 + 1] + dy * tt;
        const float pz = orig[r * 3 + 2] + dz * tt;

        accum_row(h, 0, px);
        accum_row(h, 1, py);
        accum_row(h, 2, pz);

        float sx, cx, sy, cy, sz, cz;
        sincosf(px, &sx, &cx);
        sincosf(py, &sy, &cy);
        sincosf(pz, &sz, &cz);

#pragma unroll 2
        for (int b = 0; b < POS_BANDS; b++) {
            const int k0 = 3 + 6 * b;
            accum_row(h, k0 + 0, sx);
            accum_row(h, k0 + 1, sy);
            accum_row(h, k0 + 2, sz);
            accum_row(h, k0 + 3, cx);
            accum_row(h, k0 + 4, cy);
            accum_row(h, k0 + 5, cz);
            // double the angle: s' = 2sc, c' = 1 - 2s^2
            const float nsx = 2.f * sx * cx, ncx = fmaf(-2.f * sx, sx, 1.f);
            const float nsy = 2.f * sy * cy, ncy = fmaf(-2.f * sy, sy, 1.f);
            const float nsz = 2.f * sz * cz, ncz = fmaf(-2.f * sz, sz, 1.f);
            sx = nsx; cx = ncx; sy = nsy; cy = ncy; sz = nsz; cz = ncz;
        }
    }
    // relu
#pragma unroll
    for (int q = 0; q < 32; q++) {
        h[q].f.x = fmaxf(h[q].f.x, 0.f);
        h[q].f.y = fmaxf(h[q].f.y, 0.f);
    }

    // ---- Layer 2: o[16] = b2 + h @ W2 (registers only) ----
    F2 o2[8];
#pragma unroll
    for (int cp = 0; cp < 8; cp++) o2[cp] = f2mk(b2c[2 * cp], b2c[2 * cp + 1]);
#pragma unroll
    for (int k = 0; k < HID; k++) {
        const float hv = (k & 1) ? h[k >> 1].f.y : h[k >> 1].f.x;
        const F2 hd = f2dup(hv);
#pragma unroll
        for (int q = 0; q < 4; q++) {
            const float4 w = *(const float4*)&W2c[k * 16 + 4 * q];
            fma2(o2[2 * q + 0], hd, f2mk(w.x, w.y));
            fma2(o2[2 * q + 1], hd, f2mk(w.z, w.w));
        }
    }

    // ---- extract sigma + rgb features; h and o2 die here ----
    const float sigma = fmaxf(o2[0].f.x, 0.f);
    float fv[FEAT];
#pragma unroll
    for (int k = 0; k < FEAT; k++) {
        const int col = k + 1;
        fv[k] = (col & 1) ? o2[col >> 1].f.y : o2[col >> 1].f.x;
    }

    // ---- Layers 3+4 fused, chunked over 16 columns ----
    float r0 = c2c[0], r1 = c2c[1], r2 = c2c[2];
#pragma unroll
    for (int qc = 0; qc < 4; qc++) {
        const int base = qc * 16;
        F2 gch[8];
#pragma unroll
        for (int cp = 0; cp < 8; cp++)
            gch[cp] = f2mk(sm.basev[base + 2 * cp], sm.basev[base + 2 * cp + 1]);
#pragma unroll
        for (int k = 0; k < FEAT; k++) {
            const F2 ad = f2dup(fv[k]);
#pragma unroll
            for (int q = 0; q < 4; q++) {
                const float4 w = *(const float4*)&V1c[k * HID + base + 4 * q];
                fma2(gch[2 * q + 0], ad, f2mk(w.x, w.y));
                fma2(gch[2 * q + 1], ad, f2mk(w.z, w.w));
            }
        }
#pragma unroll
        for (int j = 0; j < 16; j++) {
            const int col = base + j;
            const float gv = fmaxf((j & 1) ? gch[j >> 1].f.y : gch[j >> 1].f.x, 0.f);
            r0 += gv * V2c[col * 3 + 0];
            r1 += gv * V2c[col * 3 + 1];
            r2 += gv * V2c[col * 3 + 2];
        }
    }
    r0 = 1.f / (1.f + __expf(-r0));
    r1 = 1.f / (1.f + __expf(-r1));
    r2 = 1.f / (1.f + __expf(-r2));

    // ---- compositing ----
    {
        const float dtv = g_dt;
        const float om = __expf(-sigma * dtv);
        const float alpha = 1.f - om;

        // warp-level exclusive product scan
        float e = __shfl_up_sync(0xffffffffu, om, 1);
        if (lane == 0) e = 1.f;
        float x = e;
#pragma unroll
        for (int off = 1; off < 32; off <<= 1) {
            const float v = __shfl_up_sync(0xffffffffu, x, off);
            if (lane >= off) x *= v;
        }
        if (lane == 31) sm.wagg[warp] = x * om;
        __syncthreads();
        float pre = 1.f;
#pragma unroll
        for (int w2 = 0; w2 < 4; w2++)
            if (w2 < warp) pre *= sm.wagg[w2];
        const float Texcl = pre * x;

        const bool active = (Texcl > 1e-4f);
        const float w = active ? Texcl * alpha : 0.f;

        float cr = w * r0, cg2 = w * r1, cb = w * r2;
        float tf = active ? om : 1.f;
#pragma unroll
        for (int off = 16; off; off >>= 1) {
            cr  += __shfl_down_sync(0xffffffffu, cr,  off);
            cg2 += __shfl_down_sync(0xffffffffu, cg2, off);
            cb  += __shfl_down_sync(0xffffffffu, cb,  off);
            tf  *= __shfl_down_sync(0xffffffffu, tf,  off);
        }
        if (lane == 0) {
            sm.red[warp * 4 + 0] = cr;
            sm.red[warp * 4 + 1] = cg2;
            sm.red[warp * 4 + 2] = cb;
            sm.red[warp * 4 + 3] = tf;
        }
        __syncthreads();
        if (tid == 0) {
            out[r * 3 + 0] = sm.red[0] + sm.red[4] + sm.red[8] + sm.red[12];
            out[r * 3 + 1] = sm.red[1] + sm.red[5] + sm.red[9] + sm.red[13];
            out[r * 3 + 2] = sm.red[2] + sm.red[6] + sm.red[10] + sm.red[14];
            out[3 * N + r] = sm.red[3] * sm.red[7] * sm.red[11] * sm.red[15];
        }
    }
}

// ---------------------------------------------------------------------------
extern "C" void kernel_launch(void* const* d_in, const int* in_sizes, int n_in,
                              void* d_out, int out_size) {
    const float* orig = (const float*)d_in[0];
    const float* dirs = (const float*)d_in[1];
    const float* tmin = (const float*)d_in[2];
    const float* tmax = (const float*)d_in[3];
    const float* W1   = (const float*)d_in[4];
    const float* b1   = (const float*)d_in[5];
    const float* W2   = (const float*)d_in[6];
    const float* b2   = (const float*)d_in[7];
    const float* V1   = (const float*)d_in[8];
    const float* c1   = (const float*)d_in[9];
    const float* V2   = (const float*)d_in[10];
    const float* c2   = (const float*)d_in[11];
    float* out = (float*)d_out;
    const int N = in_sizes[2];

    cudaMemcpyToSymbolAsync(W1c, W1, D_ENC * HID * sizeof(float), 0, cudaMemcpyDeviceToDevice, 0);
    cudaMemcpyToSymbolAsync(b1c, b1, HID * sizeof(float), 0, cudaMemcpyDeviceToDevice, 0);
    cudaMemcpyToSymbolAsync(W2c, W2, HID * 16 * sizeof(float), 0, cudaMemcpyDeviceToDevice, 0);
    cudaMemcpyToSymbolAsync(b2c, b2, 16 * sizeof(float), 0, cudaMemcpyDeviceToDevice, 0);
    cudaMemcpyToSymbolAsync(V1c, V1, FEAT * HID * sizeof(float), 0, cudaMemcpyDeviceToDevice, 0);
    cudaMemcpyToSymbolAsync(V2c, V2, HID * 3 * sizeof(float), 0, cudaMemcpyDeviceToDevice, 0);
    cudaMemcpyToSymbolAsync(c2c, c2, 3 * sizeof(float), 0, cudaMemcpyDeviceToDevice, 0);

    reduce_dt_kernel<<<1, 256>>>(tmin, tmax, N);
    raymarch_kernel<<<N, SS>>>(orig, dirs, tmin, tmax, V1, c1, out, N);
}

// round 11
// speedup vs baseline: 1.6624x; 1.6624x over previous
#include <cuda_runtime.h>
#include <math.h>

#define SS 128
#define POS_BANDS 10
#define D_ENC 63
#define D_VD 27
#define HID 64
#define FEAT 15

__device__ float g_dt;

// ---- weights in constant memory (uniform-const port, off the L1tex path) ----
__constant__ float W1c[D_ENC * HID];
__constant__ float b1c[HID];
__constant__ float W2c[HID * 16];
__constant__ float b2c[16];
__constant__ float V1c[FEAT * HID];    // rows 0..14 only
__constant__ float V2c[HID * 3];
__constant__ float c2c[3];

// ---------------- packed f32x2 FMA ----------------
struct F2 { union { float2 f; unsigned long long u; }; };
__device__ __forceinline__ F2 f2mk(float x, float y) { F2 r; r.f.x = x; r.f.y = y; return r; }
__device__ __forceinline__ F2 f2dup(float x) { return f2mk(x, x); }
__device__ __forceinline__ void fma2(F2& d, const F2 a, const F2 b) {
    asm("fma.rn.f32x2 %0, %1, %2, %0;" : "+l"(d.u) : "l"(a.u), "l"(b.u));
}

// ---------------------------------------------------------------------------
__global__ void reduce_dt_kernel(const float* __restrict__ tmin,
                                 const float* __restrict__ tmax, int n) {
    __shared__ float sh[256];
    float s = 0.f;
    for (int i = threadIdx.x; i < n; i += 256) s += tmax[i] - tmin[i];
    sh[threadIdx.x] = s;
    __syncthreads();
    for (int o = 128; o > 0; o >>= 1) {
        if (threadIdx.x < o) sh[threadIdx.x] += sh[threadIdx.x + o];
        __syncthreads();
    }
    if (threadIdx.x == 0) g_dt = sh[0] / (float)n / (float)SS;
}

// ---------------------------------------------------------------------------
struct __align__(16) SmemT {
    float bufA[64 * SS];   // 32 KB: ENC^T (rows 0..62) -> H^T (rows 0..63)
    float basev[64];       // c1 + vd_enc @ V1[15:42]
    float vd[28];
    float wagg[4];
    float red[16];
};

__global__ void __launch_bounds__(SS, 4)
raymarch_kernel(const float* __restrict__ orig, const float* __restrict__ dirs,
                const float* __restrict__ tmin, const float* __restrict__ tmax,
                const float* __restrict__ V1, const float* __restrict__ c1,
                float* __restrict__ out, int N) {
    extern __shared__ char smem_raw[];
    SmemT& sm = *reinterpret_cast<SmemT*>(smem_raw);
    const int r = blockIdx.x;
    const int tid = threadIdx.x;
    const int lane = tid & 31;
    const int warp = tid >> 5;
    const int s0 = lane * 4;        // layer-1 tile: 4 samples per lane
    const int col0 = warp * 16;     // layer-1 tile: 16 columns per warp (uniform)

    const float dx = dirs[r * 3 + 0], dy = dirs[r * 3 + 1], dz = dirs[r * 3 + 2];
    const float inv = 1.f / (sqrtf(dx * dx + dy * dy + dz * dz) + 1e-8f);
    if (tid < D_VD) {
        const int p = tid / 3, c = tid % 3;
        float v = ((c == 0) ? dx : (c == 1) ? dy : dz) * inv;
        float val;
        if (p == 0) val = v;
        else {
            const int band = (p - 1) >> 1;
            float sn, cs;
            sincosf(v * (float)(1 << band), &sn, &cs);
            val = ((p - 1) & 1) ? cs : sn;
        }
        sm.vd[tid] = val;
    }
    __syncthreads();

    // ---- base = c1 + vd_enc @ V1[15:42]  (per-ray constant; coalesced LDG) ----
    if (tid < HID) {
        float acc = c1[tid];
#pragma unroll
        for (int k = 0; k < D_VD; k++) acc += sm.vd[k] * V1[(FEAT + k) * HID + tid];
        sm.basev[tid] = acc;
    }

    // ---- positional encoding -> ENC^T in bufA rows 0..62 ----
    // Band 0 via fast MUFU sin/cos (|arg| <~ 4); higher bands by angle doubling.
    {
        const float t0 = tmin[r], t1 = tmax[r];
        const float tt = t0 + (float)tid * (1.f / (SS - 1)) * (t1 - t0);
        const float p3[3] = {orig[r * 3 + 0] + dx * tt,
                             orig[r * 3 + 1] + dy * tt,
                             orig[r * 3 + 2] + dz * tt};
#pragma unroll
        for (int c = 0; c < 3; c++) {
            const float pv = p3[c];
            sm.bufA[c * SS + tid] = pv;
            float s = __sinf(pv);
            float cz = __cosf(pv);
            sm.bufA[(3 + c) * SS + tid] = s;
            sm.bufA[(6 + c) * SS + tid] = cz;
#pragma unroll
            for (int b = 1; b < POS_BANDS; b++) {
                const float s2 = 2.f * s * cz;           // sin(2a) = 2 sin cos
                const float c2 = fmaf(-2.f * s, s, 1.f); // cos(2a) = 1 - 2 sin^2
                s = s2; cz = c2;
                sm.bufA[(3 + 6 * b + c) * SS + tid] = s;
                sm.bufA[(6 + 6 * b + c) * SS + tid] = cz;
            }
        }
    }
    __syncthreads();

    // ======== Layer 1: H^T = relu(W1^T @ ENC), warp-uniform weights ========
    {
        F2 acc[4][8];   // [sample][colpair]
#pragma unroll
        for (int cp = 0; cp < 8; cp++) {
            const F2 bb = f2mk(b1c[col0 + 2 * cp], b1c[col0 + 2 * cp + 1]);
#pragma unroll
            for (int s = 0; s < 4; s++) acc[s][cp] = bb;
        }
#pragma unroll 7
        for (int k = 0; k < D_ENC; k++) {
            const float4 av = *(const float4*)&sm.bufA[k * SS + s0];
            const float4 w0 = *(const float4*)&W1c[k * HID + col0];
            const float4 w1 = *(const float4*)&W1c[k * HID + col0 + 4];
            const float4 w2 = *(const float4*)&W1c[k * HID + col0 + 8];
            const float4 w3 = *(const float4*)&W1c[k * HID + col0 + 12];
            const F2 wp[8] = {f2mk(w0.x, w0.y), f2mk(w0.z, w0.w),
                              f2mk(w1.x, w1.y), f2mk(w1.z, w1.w),
                              f2mk(w2.x, w2.y), f2mk(w2.z, w2.w),
                              f2mk(w3.x, w3.y), f2mk(w3.z, w3.w)};
            const float as[4] = {av.x, av.y, av.z, av.w};
#pragma unroll
            for (int s = 0; s < 4; s++) {
                const F2 ad = f2dup(as[s]);
#pragma unroll
                for (int cp = 0; cp < 8; cp++) fma2(acc[s][cp], ad, wp[cp]);
            }
        }
        __syncthreads();   // all ENC reads done before overwriting bufA
#pragma unroll
        for (int cp = 0; cp < 8; cp++) {
            float4 v0, v1;
            v0.x = fmaxf(acc[0][cp].f.x, 0.f); v1.x = fmaxf(acc[0][cp].f.y, 0.f);
            v0.y = fmaxf(acc[1][cp].f.x, 0.f); v1.y = fmaxf(acc[1][cp].f.y, 0.f);
            v0.z = fmaxf(acc[2][cp].f.x, 0.f); v1.z = fmaxf(acc[2][cp].f.y, 0.f);
            v0.w = fmaxf(acc[3][cp].f.x, 0.f); v1.w = fmaxf(acc[3][cp].f.y, 0.f);
            *(float4*)&sm.bufA[(col0 + 2 * cp) * SS + s0] = v0;
            *(float4*)&sm.bufA[(col0 + 2 * cp + 1) * SS + s0] = v1;
        }
    }
    __syncthreads();

    // ======== Layers 2+3+4 register-resident, one sample per thread ========
    // ---- Layer 2: o[16] = W2^T @ h ----
    F2 o2[8];
#pragma unroll
    for (int cp = 0; cp < 8; cp++) o2[cp] = f2mk(b2c[2 * cp], b2c[2 * cp + 1]);
#pragma unroll 8
    for (int k = 0; k < HID; k++) {
        const F2 hd = f2dup(sm.bufA[k * SS + tid]);
#pragma unroll
        for (int q = 0; q < 4; q++) {
            const float4 w = *(const float4*)&W2c[k * 16 + 4 * q];
            fma2(o2[2 * q + 0], hd, f2mk(w.x, w.y));
            fma2(o2[2 * q + 1], hd, f2mk(w.z, w.w));
        }
    }

    // ---- Layer 3: g[64] = base + V1a^T @ rgb_feat (all registers) ----
    F2 g[32];
#pragma unroll
    for (int cp = 0; cp < 32; cp++)
        g[cp] = f2mk(sm.basev[2 * cp], sm.basev[2 * cp + 1]);
#pragma unroll
    for (int k = 0; k < FEAT; k++) {
        const int col = k + 1;                       // rgb_feat index
        const float fv = (col & 1) ? o2[col >> 1].f.y : o2[col >> 1].f.x;
        const F2 ad = f2dup(fv);
#pragma unroll
        for (int q = 0; q < 16; q++) {
            const float4 w = *(const float4*)&V1c[k * HID + 4 * q];
            fma2(g[2 * q + 0], ad, f2mk(w.x, w.y));
            fma2(g[2 * q + 1], ad, f2mk(w.z, w.w));
        }
    }

    // ---- Layer 4: rgb = sigmoid(relu(g) @ V2 + c2)  (uniform LDCU weights) ----
    float r0 = c2c[0], r1 = c2c[1], r2 = c2c[2];
#pragma unroll 8
    for (int k = 0; k < HID; k++) {
        const float gv = fmaxf((k & 1) ? g[k >> 1].f.y : g[k >> 1].f.x, 0.f);
        r0 += gv * V2c[k * 3 + 0];
        r1 += gv * V2c[k * 3 + 1];
        r2 += gv * V2c[k * 3 + 2];
    }
    r0 = 1.f / (1.f + __expf(-r0));
    r1 = 1.f / (1.f + __expf(-r1));
    r2 = 1.f / (1.f + __expf(-r2));

    // ---- compositing ----
    {
        const float sigma = fmaxf(o2[0].f.x, 0.f);
        const float dtv = g_dt;
        const float om = __expf(-sigma * dtv);
        const float alpha = 1.f - om;

        // warp-level exclusive product scan
        float e = __shfl_up_sync(0xffffffffu, om, 1);
        if (lane == 0) e = 1.f;
        float x = e;
#pragma unroll
        for (int off = 1; off < 32; off <<= 1) {
            const float v = __shfl_up_sync(0xffffffffu, x, off);
            if (lane >= off) x *= v;
        }
        if (lane == 31) sm.wagg[warp] = x * om;
        __syncthreads();
        float pre = 1.f;
#pragma unroll
        for (int w2 = 0; w2 < 4; w2++)
            if (w2 < warp) pre *= sm.wagg[w2];
        const float Texcl = pre * x;

        const bool active = (Texcl > 1e-4f);
        const float w = active ? Texcl * alpha : 0.f;

        float cr = w * r0, cg2 = w * r1, cb = w * r2;
        float tf = active ? om : 1.f;
#pragma unroll
        for (int off = 16; off; off >>= 1) {
            cr  += __shfl_down_sync(0xffffffffu, cr,  off);
            cg2 += __shfl_down_sync(0xffffffffu, cg2, off);
            cb  += __shfl_down_sync(0xffffffffu, cb,  off);
            tf  *= __shfl_down_sync(0xffffffffu, tf,  off);
        }
        if (lane == 0) {
            sm.red[warp * 4 + 0] = cr;
            sm.red[warp * 4 + 1] = cg2;
            sm.red[warp * 4 + 2] = cb;
            sm.red[warp * 4 + 3] = tf;
        }
        __syncthreads();
        if (tid == 0) {
            out[r * 3 + 0] = sm.red[0] + sm.red[4] + sm.red[8] + sm.red[12];
            out[r * 3 + 1] = sm.red[1] + sm.red[5] + sm.red[9] + sm.red[13];
            out[r * 3 + 2] = sm.red[2] + sm.red[6] + sm.red[10] + sm.red[14];
            out[3 * N + r] = sm.red[3] * sm.red[7] * sm.red[11] * sm.red[15];
        }
    }
}

// ---------------------------------------------------------------------------
extern "C" void kernel_launch(void* const* d_in, const int* in_sizes, int n_in,
                              void* d_out, int out_size) {
    const float* orig = (const float*)d_in[0];
    const float* dirs = (const float*)d_in[1];
    const float* tmin = (const float*)d_in[2];
    const float* tmax = (const float*)d_in[3];
    const float* W1   = (const float*)d_in[4];
    const float* b1   = (const float*)d_in[5];
    const float* W2   = (const float*)d_in[6];
    const float* b2   = (const float*)d_in[7];
    const float* V1   = (const float*)d_in[8];
    const float* c1   = (const float*)d_in[9];
    const float* V2   = (const float*)d_in[10];
    const float* c2   = (const float*)d_in[11];
    float* out = (float*)d_out;
    const int N = in_sizes[2];

    cudaMemcpyToSymbolAsync(W1c, W1, D_ENC * HID * sizeof(float), 0, cudaMemcpyDeviceToDevice, 0);
    cudaMemcpyToSymbolAsync(b1c, b1, HID * sizeof(float), 0, cudaMemcpyDeviceToDevice, 0);
    cudaMemcpyToSymbolAsync(W2c, W2, HID * 16 * sizeof(float), 0, cudaMemcpyDeviceToDevice, 0);
    cudaMemcpyToSymbolAsync(b2c, b2, 16 * sizeof(float), 0, cudaMemcpyDeviceToDevice, 0);
    cudaMemcpyToSymbolAsync(V1c, V1, FEAT * HID * sizeof(float), 0, cudaMemcpyDeviceToDevice, 0);
    cudaMemcpyToSymbolAsync(V2c, V2, HID * 3 * sizeof(float), 0, cudaMemcpyDeviceToDevice, 0);
    cudaMemcpyToSymbolAsync(c2c, c2, 3 * sizeof(float), 0, cudaMemcpyDeviceToDevice, 0);

    reduce_dt_kernel<<<1, 256>>>(tmin, tmax, N);
    raymarch_kernel<<<N, SS, sizeof(SmemT)>>>(orig, dirs, tmin, tmax,
                                              V1, c1, out, N);
}

// round 14
// speedup vs baseline: 2.1551x; 1.2964x over previous
#include <cuda_runtime.h>
#include <cuda_bf16.h>
#include <math.h>
#include <cstdint>

#define SS 128
#define POS_BANDS 10
#define D_ENC 63
#define D_VD 27
#define HID 64
#define FEAT 15
#define KP 132          // padded row stride (floats) for ENC^T / H^T buffer

__device__ float g_dt;

// ---- small constants (uniform LDCU path) ----
// NOTE: every array is a multiple of 16 bytes so float4 casts below stay
// 16B-aligned regardless of declaration order (R13 lesson: c2c[3] misaligned
// W2c/V1c and trapped LDC.128).
__constant__ float b1c[HID];
__constant__ float b2c[16];
__constant__ float V2c[HID * 3];
__constant__ float c2c[4];          // 3 used + 1 pad
__constant__ float W2c[HID * 16];
__constant__ float V1c[FEAT * HID + 4];  // 960 used (960%4==0; +4 safety pad)

// ---- precomputed W1 bf16 hi/lo MMA fragments: [ (nt*4+kt)*32 + lane ] -> uint2 ----
__device__ uint2 g_bfragHi[1024];
__device__ uint2 g_bfragLo[1024];

// ---------------- packed f32x2 FMA (layers 2-4) ----------------
struct F2 { union { float2 f; unsigned long long u; }; };
__device__ __forceinline__ F2 f2mk(float x, float y) { F2 r; r.f.x = x; r.f.y = y; return r; }
__device__ __forceinline__ F2 f2dup(float x) { return f2mk(x, x); }
__device__ __forceinline__ void fma2(F2& d, const F2 a, const F2 b) {
    asm("fma.rn.f32x2 %0, %1, %2, %0;" : "+l"(d.u) : "l"(a.u), "l"(b.u));
}

// ---------------- bf16 split helpers ----------------
__device__ __forceinline__ uint32_t pack_split(float v0, float v1, uint32_t& lo) {
    __nv_bfloat162 h = __floats2bfloat162_rn(v0, v1);        // .x = v0 (low), .y = v1 (high)
    const float q0 = __bfloat162float(h.x), q1 = __bfloat162float(h.y);
    __nv_bfloat162 l = __floats2bfloat162_rn(v0 - q0, v1 - q1);
    lo = *(uint32_t*)&l;
    return *(uint32_t*)&h;
}

__device__ __forceinline__ void mma_bf16(float* d, const uint32_t* a, uint32_t b0, uint32_t b1) {
    asm volatile(
        "mma.sync.aligned.m16n8k16.row.col.f32.bf16.bf16.f32 "
        "{%0,%1,%2,%3}, {%4,%5,%6,%7}, {%8,%9}, {%0,%1,%2,%3};"
        : "+f"(d[0]), "+f"(d[1]), "+f"(d[2]), "+f"(d[3])
        : "r"(a[0]), "r"(a[1]), "r"(a[2]), "r"(a[3]), "r"(b0), "r"(b1));
}

// ---------------------------------------------------------------------------
// setup: dt + W1 fragment precompute (lane-exact layout for m16n8k16 .col B)
// ---------------------------------------------------------------------------
__global__ void setup_kernel(const float* __restrict__ tmin, const float* __restrict__ tmax,
                             const float* __restrict__ W1, int n) {
    const int tid = threadIdx.x;
    __shared__ float sh[256];
    float s = 0.f;
    for (int i = tid; i < n; i += 256) s += tmax[i] - tmin[i];
    sh[tid] = s;
    __syncthreads();
    for (int o = 128; o > 0; o >>= 1) {
        if (tid < o) sh[tid] += sh[tid + o];
        __syncthreads();
    }
    if (tid == 0) g_dt = sh[0] / (float)n / (float)SS;

    // B fragment: reg0 = {B(k0,n), B(k0+1,n)}, reg1 = {B(k0+8,n), B(k0+9,n)}
    // with B(k,n) = W1[k*HID+n] (k==63 -> 0), k0 = kt*16 + tig*2, n = nt*8 + gid
    for (int i = tid; i < 1024; i += 256) {
        const int frag = i >> 5, lane = i & 31;
        const int nt = frag >> 2, kt = frag & 3;
        const int gid = lane >> 2, tig = lane & 3;
        const int nn = nt * 8 + gid;
        const int k0 = kt * 16 + tig * 2;
        const float v0 = W1[k0 * HID + nn];            // k0   <= 54
        const float v1 = W1[(k0 + 1) * HID + nn];      // k0+1 <= 55
        const float v2 = W1[(k0 + 8) * HID + nn];      // k0+8 <= 62
        const float v3 = (k0 + 9 < D_ENC) ? W1[(k0 + 9) * HID + nn] : 0.f;  // 63 -> pad
        uint32_t l0, l1;
        const uint32_t h0 = pack_split(v0, v1, l0);
        const uint32_t h1 = pack_split(v2, v3, l1);
        g_bfragHi[i] = make_uint2(h0, h1);
        g_bfragLo[i] = make_uint2(l0, l1);
    }
}

// ---------------------------------------------------------------------------
struct __align__(16) SmemT {
    float bufA[64 * KP];    // ENC^T -> H^T (row stride KP floats)
    uint2 bH[1024];         // W1 hi fragments
    uint2 bL[1024];         // W1 lo fragments
    float basev[64];
    float vd[28];
    float wagg[4];
    float red[16];
};

__global__ void __launch_bounds__(SS, 3)
raymarch_kernel(const float* __restrict__ orig, const float* __restrict__ dirs,
                const float* __restrict__ tmin, const float* __restrict__ tmax,
                const float* __restrict__ V1, const float* __restrict__ c1,
                float* __restrict__ out, int N) {
    extern __shared__ char smem_raw[];
    SmemT& sm = *reinterpret_cast<SmemT*>(smem_raw);
    const int r = blockIdx.x;
    const int tid = threadIdx.x;
    const int lane = tid & 31;
    const int warp = tid >> 5;
    const int gid = lane >> 2;      // mma group id (0..7)
    const int tig = lane & 3;       // thread-in-group (0..3)

    // ---- stage W1 fragments to shared ----
    for (int i = tid; i < 1024; i += SS) {
        sm.bH[i] = g_bfragHi[i];
        sm.bL[i] = g_bfragLo[i];
    }

    // ---- view-dir encoding ----
    const float dx = dirs[r * 3 + 0], dy = dirs[r * 3 + 1], dz = dirs[r * 3 + 2];
    const float inv = 1.f / (sqrtf(dx * dx + dy * dy + dz * dz) + 1e-8f);
    if (tid < D_VD) {
        const int p = tid / 3, c = tid % 3;
        float v = ((c == 0) ? dx : (c == 1) ? dy : dz) * inv;
        float val;
        if (p == 0) val = v;
        else {
            const int band = (p - 1) >> 1;
            float sn, cs;
            sincosf(v * (float)(1 << band), &sn, &cs);
            val = ((p - 1) & 1) ? cs : sn;
        }
        sm.vd[tid] = val;
    }
    __syncthreads();

    // ---- base = c1 + vd_enc @ V1[15:42] ----
    if (tid < HID) {
        float acc = c1[tid];
#pragma unroll
        for (int k = 0; k < D_VD; k++) acc += sm.vd[k] * V1[(FEAT + k) * HID + tid];
        sm.basev[tid] = acc;
    }

    // ---- positional encoding -> ENC^T (rows k, stride KP), angle doubling ----
    {
        const float t0 = tmin[r], t1 = tmax[r];
        const float tt = t0 + (float)tid * (1.f / (SS - 1)) * (t1 - t0);
        const float p3[3] = {orig[r * 3 + 0] + dx * tt,
                             orig[r * 3 + 1] + dy * tt,
                             orig[r * 3 + 2] + dz * tt};
#pragma unroll
        for (int c = 0; c < 3; c++) {
            const float pv = p3[c];
            sm.bufA[c * KP + tid] = pv;
            float s = __sinf(pv), cz = __cosf(pv);
            sm.bufA[(3 + c) * KP + tid] = s;
            sm.bufA[(6 + c) * KP + tid] = cz;
#pragma unroll
            for (int b = 1; b < POS_BANDS; b++) {
                const float s2 = 2.f * s * cz;
                const float c2 = fmaf(-2.f * s, s, 1.f);
                s = s2; cz = c2;
                sm.bufA[(3 + 6 * b + c) * KP + tid] = s;
                sm.bufA[(6 + 6 * b + c) * KP + tid] = cz;
            }
        }
        sm.bufA[63 * KP + tid] = 0.f;   // zero pad column k=63
    }
    __syncthreads();

    // ======== Layer 1 via mma.sync bf16 3-way split ========
    // Each warp owns 32 rows (samples); D[2 m-tiles][8 n-tiles][4]
    {
        float d[2][8][4];
#pragma unroll
        for (int mt = 0; mt < 2; mt++)
#pragma unroll
            for (int nt = 0; nt < 8; nt++)
#pragma unroll
                for (int j = 0; j < 4; j++) d[mt][nt][j] = 0.f;

#pragma unroll
        for (int kt = 0; kt < 4; kt++) {
            uint32_t ahi[2][4], alo[2][4];
            const int c0 = kt * 16 + tig * 2;
#pragma unroll
            for (int mt = 0; mt < 2; mt++) {
                const int ra = warp * 32 + mt * 16 + gid;
                const int rb = ra + 8;
                const float v00 = sm.bufA[(c0    ) * KP + ra];
                const float v01 = sm.bufA[(c0 + 1) * KP + ra];
                const float v10 = sm.bufA[(c0    ) * KP + rb];
                const float v11 = sm.bufA[(c0 + 1) * KP + rb];
                const float v02 = sm.bufA[(c0 + 8) * KP + ra];
                const float v03 = sm.bufA[(c0 + 9) * KP + ra];
                const float v12 = sm.bufA[(c0 + 8) * KP + rb];
                const float v13 = sm.bufA[(c0 + 9) * KP + rb];
                ahi[mt][0] = pack_split(v00, v01, alo[mt][0]);
                ahi[mt][1] = pack_split(v10, v11, alo[mt][1]);
                ahi[mt][2] = pack_split(v02, v03, alo[mt][2]);
                ahi[mt][3] = pack_split(v12, v13, alo[mt][3]);
            }
#pragma unroll
            for (int nt = 0; nt < 8; nt++) {
                const uint2 bh = sm.bH[(nt * 4 + kt) * 32 + lane];
                const uint2 bl = sm.bL[(nt * 4 + kt) * 32 + lane];
#pragma unroll
                for (int mt = 0; mt < 2; mt++) {
                    mma_bf16(d[mt][nt], ahi[mt], bh.x, bh.y);
                    mma_bf16(d[mt][nt], ahi[mt], bl.x, bl.y);
                    mma_bf16(d[mt][nt], alo[mt], bh.x, bh.y);
                }
            }
        }

        // epilogue: H^T = relu(D + b1) back into bufA (own rows only -> no race)
#pragma unroll
        for (int mt = 0; mt < 2; mt++) {
            const int ra = warp * 32 + mt * 16 + gid;
            const int rb = ra + 8;
#pragma unroll
            for (int nt = 0; nt < 8; nt++) {
                const int col = nt * 8 + tig * 2;
                const float bA = b1c[col], bB = b1c[col + 1];
                sm.bufA[col * KP + ra]       = fmaxf(d[mt][nt][0] + bA, 0.f);
                sm.bufA[(col + 1) * KP + ra] = fmaxf(d[mt][nt][1] + bB, 0.f);
                sm.bufA[col * KP + rb]       = fmaxf(d[mt][nt][2] + bA, 0.f);
                sm.bufA[(col + 1) * KP + rb] = fmaxf(d[mt][nt][3] + bB, 0.f);
            }
        }
    }
    __syncthreads();

    // ======== Layers 2+3+4 register-resident, one sample per thread ========
    F2 o2[8];
#pragma unroll
    for (int cp = 0; cp < 8; cp++) o2[cp] = f2mk(b2c[2 * cp], b2c[2 * cp + 1]);
#pragma unroll 8
    for (int k = 0; k < HID; k++) {
        const F2 hd = f2dup(sm.bufA[k * KP + tid]);
#pragma unroll
        for (int q = 0; q < 4; q++) {
            const float4 w = *(const float4*)&W2c[k * 16 + 4 * q];
            fma2(o2[2 * q + 0], hd, f2mk(w.x, w.y));
            fma2(o2[2 * q + 1], hd, f2mk(w.z, w.w));
        }
    }

    F2 g[32];
#pragma unroll
    for (int cp = 0; cp < 32; cp++)
        g[cp] = f2mk(sm.basev[2 * cp], sm.basev[2 * cp + 1]);
#pragma unroll
    for (int k = 0; k < FEAT; k++) {
        const int col = k + 1;
        const float fv = (col & 1) ? o2[col >> 1].f.y : o2[col >> 1].f.x;
        const F2 ad = f2dup(fv);
#pragma unroll
        for (int q = 0; q < 16; q++) {
            const float4 w = *(const float4*)&V1c[k * HID + 4 * q];
            fma2(g[2 * q + 0], ad, f2mk(w.x, w.y));
            fma2(g[2 * q + 1], ad, f2mk(w.z, w.w));
        }
    }

    float r0 = c2c[0], r1 = c2c[1], r2 = c2c[2];
#pragma unroll 8
    for (int k = 0; k < HID; k++) {
        const float gv = fmaxf((k & 1) ? g[k >> 1].f.y : g[k >> 1].f.x, 0.f);
        r0 += gv * V2c[k * 3 + 0];
        r1 += gv * V2c[k * 3 + 1];
        r2 += gv * V2c[k * 3 + 2];
    }
    r0 = 1.f / (1.f + __expf(-r0));
    r1 = 1.f / (1.f + __expf(-r1));
    r2 = 1.f / (1.f + __expf(-r2));

    // ---- compositing ----
    {
        const float sigma = fmaxf(o2[0].f.x, 0.f);
        const float dtv = g_dt;
        const float om = __expf(-sigma * dtv);
        const float alpha = 1.f - om;

        float e = __shfl_up_sync(0xffffffffu, om, 1);
        if (lane == 0) e = 1.f;
        float x = e;
#pragma unroll
        for (int off = 1; off < 32; off <<= 1) {
            const float v = __shfl_up_sync(0xffffffffu, x, off);
            if (lane >= off) x *= v;
        }
        if (lane == 31) sm.wagg[warp] = x * om;
        __syncthreads();
        float pre = 1.f;
#pragma unroll
        for (int w2 = 0; w2 < 4; w2++)
            if (w2 < warp) pre *= sm.wagg[w2];
        const float Texcl = pre * x;

        const bool active = (Texcl > 1e-4f);
        const float w = active ? Texcl * alpha : 0.f;

        float cr = w * r0, cg2 = w * r1, cb = w * r2;
        float tf = active ? om : 1.f;
#pragma unroll
        for (int off = 16; off; off >>= 1) {
            cr  += __shfl_down_sync(0xffffffffu, cr,  off);
            cg2 += __shfl_down_sync(0xffffffffu, cg2, off);
            cb  += __shfl_down_sync(0xffffffffu, cb,  off);
            tf  *= __shfl_down_sync(0xffffffffu, tf,  off);
        }
        if (lane == 0) {
            sm.red[warp * 4 + 0] = cr;
            sm.red[warp * 4 + 1] = cg2;
            sm.red[warp * 4 + 2] = cb;
            sm.red[warp * 4 + 3] = tf;
        }
        __syncthreads();
        if (tid == 0) {
            out[r * 3 + 0] = sm.red[0] + sm.red[4] + sm.red[8] + sm.red[12];
            out[r * 3 + 1] = sm.red[1] + sm.red[5] + sm.red[9] + sm.red[13];
            out[r * 3 + 2] = sm.red[2] + sm.red[6] + sm.red[10] + sm.red[14];
            out[3 * N + r] = sm.red[3] * sm.red[7] * sm.red[11] * sm.red[15];
        }
    }
}

// ---------------------------------------------------------------------------
extern "C" void kernel_launch(void* const* d_in, const int* in_sizes, int n_in,
                              void* d_out, int out_size) {
    const float* orig = (const float*)d_in[0];
    const float* dirs = (const float*)d_in[1];
    const float* tmin = (const float*)d_in[2];
    const float* tmax = (const float*)d_in[3];
    const float* W1   = (const float*)d_in[4];
    const float* b1   = (const float*)d_in[5];
    const float* W2   = (const float*)d_in[6];
    const float* b2   = (const float*)d_in[7];
    const float* V1   = (const float*)d_in[8];
    const float* c1   = (const float*)d_in[9];
    const float* V2   = (const float*)d_in[10];
    const float* c2   = (const float*)d_in[11];
    float* out = (float*)d_out;
    const int N = in_sizes[2];

    cudaMemcpyToSymbolAsync(b1c, b1, HID * sizeof(float), 0, cudaMemcpyDeviceToDevice, 0);
    cudaMemcpyToSymbolAsync(b2c, b2, 16 * sizeof(float), 0, cudaMemcpyDeviceToDevice, 0);
    cudaMemcpyToSymbolAsync(W2c, W2, HID * 16 * sizeof(float), 0, cudaMemcpyDeviceToDevice, 0);
    cudaMemcpyToSymbolAsync(V1c, V1, FEAT * HID * sizeof(float), 0, cudaMemcpyDeviceToDevice, 0);
    cudaMemcpyToSymbolAsync(V2c, V2, HID * 3 * sizeof(float), 0, cudaMemcpyDeviceToDevice, 0);
    cudaMemcpyToSymbolAsync(c2c, c2, 3 * sizeof(float), 0, cudaMemcpyDeviceToDevice, 0);

    cudaFuncSetAttribute(raymarch_kernel,
                         cudaFuncAttributeMaxDynamicSharedMemorySize, (int)sizeof(SmemT));

    setup_kernel<<<1, 256>>>(tmin, tmax, W1, N);
    raymarch_kernel<<<N, SS, sizeof(SmemT)>>>(orig, dirs, tmin, tmax, V1, c1, out, N);
}